// round 17
// baseline (speedup 1.0000x reference)
#include <cuda_runtime.h>
#include <cuda_bf16.h>

#define NSETS 8
#define NPTS  4096
#define DF    16
#define KK    16
#define QT    128                 // threads per block == queries per block
#define CT    64                  // candidate tile size
#define NTILES (NPTS / CT)        // 64
#define NQ    (NSETS * NPTS)      // 32768
#define DS    66                  // D smem row stride in floats (even: STS.64 ok)
#define BUFN  12
#define FLUSH_AT 8                // vote every 4: max cnt 7+4=11 <= 12

typedef unsigned long long u64;
typedef unsigned int u32;

// ---- device scratch (no allocs allowed) ----
// per point: 64 bf16 = [a0..15 | b0..15 | c0..15 | 0 x16]  (128 B row)
__device__ __nv_bfloat16 g_limbs[(size_t)NQ * 64];
__device__ float         g_norms[NQ];

// m16n8k16 row.col bf16 MMA, fp32 accumulate (sm_80+ PTX, compiles on compute_103)
__device__ __forceinline__ void mma16816(float* c, const u32* a, const u32* b) {
    asm("mma.sync.aligned.m16n8k16.row.col.f32.bf16.bf16.f32 "
        "{%0,%1,%2,%3}, {%4,%5,%6,%7}, {%8,%9}, {%0,%1,%2,%3};"
        : "+f"(c[0]), "+f"(c[1]), "+f"(c[2]), "+f"(c[3])
        : "r"(a[0]), "r"(a[1]), "r"(a[2]), "r"(a[3]), "r"(b[0]), "r"(b[1]));
}

// ===================== prep: 3-limb bf16 split + norms =====================
__global__ __launch_bounds__(128) void knn_prep(const float* __restrict__ x) {
    const int p = blockIdx.x * 128 + threadIdx.x;   // global point id
    const float4* xp = reinterpret_cast<const float4*>(x + (size_t)p * DF);
    float v[16];
    {
        float4 w0 = xp[0], w1 = xp[1], w2 = xp[2], w3 = xp[3];
        v[0]=w0.x; v[1]=w0.y; v[2]=w0.z; v[3]=w0.w;
        v[4]=w1.x; v[5]=w1.y; v[6]=w1.z; v[7]=w1.w;
        v[8]=w2.x; v[9]=w2.y; v[10]=w2.z; v[11]=w2.w;
        v[12]=w3.x; v[13]=w3.y; v[14]=w3.z; v[15]=w3.w;
    }
    float n = 0.0f;
#pragma unroll
    for (int i = 0; i < 16; ++i) n = fmaf(v[i], v[i], n);
    g_norms[p] = n;

    __nv_bfloat16 row[64];
#pragma unroll
    for (int i = 0; i < 16; ++i) {
        __nv_bfloat16 a = __float2bfloat16(v[i]);
        float r1 = v[i] - __bfloat162float(a);
        __nv_bfloat16 b = __float2bfloat16(r1);
        float r2 = r1 - __bfloat162float(b);
        __nv_bfloat16 c = __float2bfloat16(r2);
        row[i] = a; row[16 + i] = b; row[32 + i] = c;
        row[48 + i] = __float2bfloat16(0.0f);
    }
    uint4* dst = reinterpret_cast<uint4*>(g_limbs + (size_t)p * 64);
    const uint4* src = reinterpret_cast<const uint4*>(row);
#pragma unroll
    for (int i = 0; i < 8; ++i) dst[i] = src[i];
}

// ===================== main: HMMA distances + per-warp top-k =====================
__global__ __launch_bounds__(QT) void knn_mma(float* __restrict__ out) {
    __shared__ float sD[QT][DS];          // lhs = cn - 2*dot, one row per query
    __shared__ u64   sBuf[BUFN][QT];      // per-thread append buffers

    const int tid  = threadIdx.x;
    const int w    = tid >> 5;            // warp id: owns query rows [w*32, w*32+32)
    const int lane = tid & 31;
    const int gp   = lane >> 2;           // group id (0..7)
    const int tg   = lane & 3;            // thread-in-group (0..3)

    const int set   = blockIdx.y;
    const int qbase = blockIdx.x * QT;    // first query of block (within set)
    const int qi    = qbase + tid;
    const int g     = set * NPTS + qi;    // global query id

    // ---- load A fragments once: 2 rowtiles x 3 limbs x 4 regs = 24 regs ----
    u32 A[2][3][4];
#pragma unroll
    for (int rt = 0; rt < 2; ++rt) {
        const int qrow = set * NPTS + qbase + w * 32 + rt * 16 + gp;
        const u32* r0 = reinterpret_cast<const u32*>(g_limbs + (size_t)qrow * 64);
        const u32* r1 = r0 + 8 * 32;   // +8 rows (32 u32 per row)
#pragma unroll
        for (int l = 0; l < 3; ++l) {
            A[rt][l][0] = r0[l * 8 + tg];
            A[rt][l][1] = r1[l * 8 + tg];
            A[rt][l][2] = r0[l * 8 + tg + 4];
            A[rt][l][3] = r1[l * 8 + tg + 4];
        }
    }
    const float qn = g_norms[g];

    // ---- top-k in lhs space (monotone transform of distance) ----
    float bestL[KK]; int bestI[KK];
#pragma unroll
    for (int t = 0; t < KK; ++t) { bestL[t] = __int_as_float(0x7f800000); bestI[t] = 0; }
    float threshL = __int_as_float(0x7f800000);
    int cnt = 0;
    const u32 sBufAddr = (u32)__cvta_generic_to_shared(&sBuf[0][tid]);

    auto flush = [&]() {
        for (int b = 0; b < cnt; ++b) {
            u64 key = sBuf[b][tid];
            u32 iu; float d;
            asm("mov.b64 {%0, %1}, %2;" : "=r"(iu), "=f"(d) : "l"(key));
            if (d < bestL[KK - 1]) {
                const int idx = (int)iu;
#pragma unroll
                for (int t = KK - 1; t >= 1; --t) {
                    const bool shift = d < bestL[t - 1];
                    const bool here  = d < bestL[t];
                    bestL[t] = shift ? bestL[t - 1] : (here ? d : bestL[t]);
                    bestI[t] = shift ? bestI[t - 1] : (here ? idx : bestI[t]);
                }
                if (d < bestL[0]) { bestL[0] = d; bestI[0] = idx; }
            }
        }
        cnt = 0;
        threshL = bestL[KK - 1];
    };

    for (int tile = 0; tile < NTILES; ++tile) {
        const int cbase = tile * CT;      // within set
        // ---- compute this warp's 32xCT strip of lhs into sD ----
#pragma unroll 2
        for (int ct = 0; ct < CT / 8; ++ct) {
            const int cnd = set * NPTS + cbase + ct * 8;
            // B fragments: 3 limbs x 2 regs (col = gp, k pairs = tg)
            const u32* br = reinterpret_cast<const u32*>(g_limbs + (size_t)(cnd + gp) * 64);
            u32 B[3][2];
#pragma unroll
            for (int l = 0; l < 3; ++l) { B[l][0] = br[l * 8 + tg]; B[l][1] = br[l * 8 + tg + 4]; }
            // candidate norms for this thread's output cols (2tg, 2tg+1)
            const float cnA = g_norms[cnd + 2 * tg];
            const float cnB = g_norms[cnd + 2 * tg + 1];

            float acc0[4] = {0.f, 0.f, 0.f, 0.f};
            float acc1[4] = {0.f, 0.f, 0.f, 0.f};
            // 6 significant limb pairs: aa, ab, ba, ac, ca, bb
            mma16816(acc0, A[0][0], B[0]);
            mma16816(acc1, A[1][0], B[0]);
            mma16816(acc0, A[0][0], B[1]);
            mma16816(acc1, A[1][0], B[1]);
            mma16816(acc0, A[0][1], B[0]);
            mma16816(acc1, A[1][1], B[0]);
            mma16816(acc0, A[0][0], B[2]);
            mma16816(acc1, A[1][0], B[2]);
            mma16816(acc0, A[0][2], B[0]);
            mma16816(acc1, A[1][2], B[0]);
            mma16816(acc0, A[0][1], B[1]);
            mma16816(acc1, A[1][1], B[1]);

            // fold candidate norm: lhs = cn - 2*dot ; store pairs (cols 2tg,2tg+1)
            const int col = ct * 8 + 2 * tg;
            const int r0 = w * 32 + gp;
            *reinterpret_cast<float2*>(&sD[r0][col]) =
                make_float2(fmaf(-2.f, acc0[0], cnA), fmaf(-2.f, acc0[1], cnB));
            *reinterpret_cast<float2*>(&sD[r0 + 8][col]) =
                make_float2(fmaf(-2.f, acc0[2], cnA), fmaf(-2.f, acc0[3], cnB));
            *reinterpret_cast<float2*>(&sD[r0 + 16][col]) =
                make_float2(fmaf(-2.f, acc1[0], cnA), fmaf(-2.f, acc1[1], cnB));
            *reinterpret_cast<float2*>(&sD[r0 + 24][col]) =
                make_float2(fmaf(-2.f, acc1[2], cnA), fmaf(-2.f, acc1[3], cnB));
        }
        __syncwarp();

        // ---- epilogue: scan own row (query tid), branch-free append ----
        const float* row = sD[tid];
        for (int j0 = 0; j0 < CT; j0 += 4) {
#pragma unroll
            for (int u = 0; u < 4; ++u) {
                const int j = j0 + u;
                const float lhs = row[j];
                const int idx = cbase + j;
                u64 key;
                asm("mov.b64 %0, {%1, %2};" : "=l"(key) : "r"(idx), "f"(lhs));
                const u32 saddr = sBufAddr + (u32)cnt * (QT * 8);
                asm volatile(
                    "{\n\t.reg .pred p;\n\t"
                    "setp.lt.f32 p, %1, %2;\n\t"
                    "@p st.shared.b64 [%0], %3;\n\t}"
                    :: "r"(saddr), "f"(lhs), "f"(threshL), "l"(key) : "memory");
                cnt += (lhs < threshL) ? 1 : 0;
            }
            if (__any_sync(0xffffffffu, cnt >= FLUSH_AT)) flush();
        }
        __syncwarp();   // WAR: next tile overwrites rows other lanes just read
    }
    if (__any_sync(0xffffffffu, cnt > 0)) flush();

    // ---- emit [src | dst | dist]; d = qn + lhs ----
    {
        const int base = set * NPTS;
        const size_t stride = (size_t)NQ * KK;
        float4* o_src = reinterpret_cast<float4*>(out + (size_t)g * KK);
        float4* o_dst = reinterpret_cast<float4*>(out + stride + (size_t)g * KK);
        float4* o_dis = reinterpret_cast<float4*>(out + 2 * stride + (size_t)g * KK);
        const float sv = (float)g;
#pragma unroll
        for (int t = 0; t < KK; t += 4) {
            o_src[t / 4] = make_float4(sv, sv, sv, sv);
            o_dst[t / 4] = make_float4((float)(base + bestI[t + 0]),
                                       (float)(base + bestI[t + 1]),
                                       (float)(base + bestI[t + 2]),
                                       (float)(base + bestI[t + 3]));
            o_dis[t / 4] = make_float4(qn + bestL[t + 0], qn + bestL[t + 1],
                                       qn + bestL[t + 2], qn + bestL[t + 3]);
        }
    }
}

extern "C" void kernel_launch(void* const* d_in, const int* in_sizes, int n_in,
                              void* d_out, int out_size) {
    const float* x = (const float*)d_in[0];
    float* out = (float*)d_out;

    knn_prep<<<NQ / 128, 128>>>(x);
    dim3 grid(NPTS / QT, NSETS);
    knn_mma<<<grid, QT>>>(out);
}